// round 13
// baseline (speedup 1.0000x reference)
#include <cuda_runtime.h>
#include <cuda_fp16.h>
#include <cstdint>

// ============================================================================
// DifferentiableXGB — base-arch (compute_103), mixed-granularity grid.
// GEMM: split[B,400] = x[32768,1024] @ W1^T via mma.sync m16n8k16 f32.f16 —
// measured dispatch floor ~15-16 cyc/HMMA/SMSP; this round attacks the two
// non-pipe losses: wave quantization (256 CTAs on 148 SMs = 86.5%) and the
// 416-col padding (3.8% wasted MMAs).
// Work = 512 half-units (tile x tree-group, BN=200 exact). Grid = 444 CTAs,
// longest-first: CTAs 0..67 run both groups of tiles 0..67 (write out + FC
// directly); CTAs 68..443 run one (tile,group) each (write g_part partials);
// final kernel FCs rows >= 8704. Greedy packing -> ~97% SM efficiency.
// ============================================================================

static constexpr int BTOT  = 32768;
static constexpr int Dk    = 1024;
static constexpr int NCOL  = 400;
static constexpr int BN    = 200;    // cols per pass (50 trees) — exact, no pad
static constexpr int BM    = 128;
static constexpr int KC    = 64;     // k-chunk: 64 fp16 = 128B row (SW128)
static constexpr int NCHUNK= 16;
static constexpr int NT    = 256;
static constexpr int NDBL  = 68;     // tiles with double-unit CTAs
static constexpr int ROWSPLIT = NDBL * BM;   // 8704: rows below -> direct out

// smem byte offsets
static constexpr int S_BIAS = 0;        // 400 f = 1600 B
static constexpr int S_FW   = 1600;     // 100 fw + 8 fcw + 2 fcb
static constexpr int S_RED  = 2048;     // 512 f
static constexpr int S_A0   = 8192;     // 128*128B = 16384
static constexpr int S_A1   = 24576;
static constexpr int S_B0   = 40960;    // 200*128B = 25600
static constexpr int S_B1   = 66560;
static constexpr int S_TOTAL= 92160;

#define SW(o) ((o) ^ (((o) >> 3) & 0x70))

__device__ __align__(16) __half g_Wh[NCOL * Dk];   // 800 KB fp16 W scratch
__device__ float g_part[2][BTOT][4];                // 1 MB partials (rows>=8704)

// ---------------- asm helpers (all base-arch) ----------------
__device__ __forceinline__ uint32_t smem_u32(const void* p) {
    uint32_t a;
    asm("{ .reg .u64 t; cvta.to.shared.u64 t, %1; cvt.u32.u64 %0, t; }" : "=r"(a) : "l"(p));
    return a;
}
__device__ __forceinline__ void ldsm_x4(uint32_t (&r)[4], uint32_t addr) {
    asm volatile("ldmatrix.sync.aligned.m8n8.x4.shared.b16 {%0,%1,%2,%3}, [%4];"
                 : "=r"(r[0]), "=r"(r[1]), "=r"(r[2]), "=r"(r[3]) : "r"(addr));
}
__device__ __forceinline__ void ldsm_x2(uint32_t (&r)[2], uint32_t addr) {
    asm volatile("ldmatrix.sync.aligned.m8n8.x2.shared.b16 {%0,%1}, [%2];"
                 : "=r"(r[0]), "=r"(r[1]) : "r"(addr));
}
__device__ __forceinline__ void mma16816(float (&c)[4], const uint32_t (&a)[4],
                                         uint32_t b0, uint32_t b1) {
    asm volatile("mma.sync.aligned.m16n8k16.row.col.f32.f16.f16.f32 "
                 "{%0,%1,%2,%3}, {%4,%5,%6,%7}, {%8,%9}, {%0,%1,%2,%3};"
                 : "+f"(c[0]), "+f"(c[1]), "+f"(c[2]), "+f"(c[3])
                 : "r"(a[0]), "r"(a[1]), "r"(a[2]), "r"(a[3]), "r"(b0), "r"(b1));
}
__device__ __forceinline__ void cp16(uint32_t dst, const void* src) {
    asm volatile("cp.async.cg.shared.global [%0], [%1], 16;" :: "r"(dst), "l"(src));
}
__device__ __forceinline__ float sig_t(float v) {   // sigmoid via 1 MUFU (tanh)
    float t;
    asm("tanh.approx.f32 %0, %1;" : "=f"(t) : "f"(v * 0.5f));
    return fmaf(t, 0.5f, 0.5f);
}

// ---------------- kernel 1: W1 fp32 -> fp16 (exact 400 rows) ----------------
__global__ void xgb_conv_w(const float* __restrict__ W1) {
    int idx = blockIdx.x * 256 + threadIdx.x;      // 400*256 = 102400 uint2
    float4 v = reinterpret_cast<const float4*>(W1)[idx];
    __half2 p0 = __float22half2_rn(make_float2(v.x, v.y));
    __half2 p1 = __float22half2_rn(make_float2(v.z, v.w));
    uint2 o;
    o.x = *reinterpret_cast<uint32_t*>(&p0);
    o.y = *reinterpret_cast<uint32_t*>(&p1);
    reinterpret_cast<uint2*>(g_Wh)[idx] = o;
}

// ---------------- kernel 2: GEMM + fused tree epilogue (+FC for 2-pass) -----
__global__ void __launch_bounds__(NT, 1)
xgb_main(const float* __restrict__ x, const float* __restrict__ b1,
         const float* __restrict__ fw, const float* __restrict__ fcw,
         const float* __restrict__ fcb, float* __restrict__ out) {
    extern __shared__ char smem[];
    const uint32_t smb = smem_u32(smem);
    const int tid  = threadIdx.x;
    const int lane = tid & 31;
    const int wid  = tid >> 5;
    const int warpM = wid & 3, warpN = wid >> 2;   // 4 x 2
    const int q  = lane & 3;     // col quad within n8 block
    const int rq = lane >> 2;    // row within 8
    // warpN0 owns 104 cols (13 blocks incl. x2 tail), warpN1 owns 96 (12 blocks)
    const int nblk = (warpN == 0) ? 13 : 12;

    // work assignment: longest jobs first
    int tile, g0, ng;
    if (blockIdx.x < NDBL) { tile = blockIdx.x;                 g0 = 0;                ng = 2; }
    else { const int u = blockIdx.x - NDBL; tile = NDBL + (u >> 1); g0 = u & 1;        ng = 1; }
    const int row0 = tile * BM;

    // constants to smem
    float* bias_sm = reinterpret_cast<float*>(smem + S_BIAS);
    float* fw_sm   = reinterpret_cast<float*>(smem + S_FW);
    for (int i = tid; i < NCOL; i += NT) bias_sm[i] = b1[i];
    if (tid < 100) fw_sm[tid] = fw[tid];
    if (tid < 8)   fw_sm[100 + tid] = fcw[tid];
    if (tid < 2)   fw_sm[108 + tid] = fcb[tid];

    float wac[4][2] = {{0.f,0.f},{0.f,0.f},{0.f,0.f},{0.f,0.f}};
    int g = g0;

    for (int gi = 0; gi < ng; ++gi, ++g) {
        const __half* wsrc = g_Wh + (size_t)g * BN * Dk;

        // ---- prologue: chunk 0 ----
        float4 av[8];
        const int f4 = tid & 15, rb = tid >> 4;
        const float* xb0 = x + (size_t)(row0 + rb) * Dk + f4 * 4;
        #pragma unroll
        for (int r = 0; r < 8; ++r)
            av[r] = *reinterpret_cast<const float4*>(xb0 + (size_t)r * 16 * Dk);
        for (int i = tid; i < BN * 8; i += NT) {           // B(0) -> buf0
            const int row = i >> 3, c16 = i & 7;
            const uint32_t off = (uint32_t)(row * 128 + c16 * 16);
            cp16(smb + S_B0 + SW(off), wsrc + (size_t)row * Dk + c16 * 8);
        }
        asm volatile("cp.async.commit_group;" ::: "memory");
        #pragma unroll
        for (int r = 0; r < 8; ++r) {                      // A(0) -> buf0
            __half2 p0 = __float22half2_rn(make_float2(av[r].x, av[r].y));
            __half2 p1 = __float22half2_rn(make_float2(av[r].z, av[r].w));
            uint2 val;
            val.x = *reinterpret_cast<uint32_t*>(&p0);
            val.y = *reinterpret_cast<uint32_t*>(&p1);
            const uint32_t off = (uint32_t)((rb + 16 * r) * 128 + f4 * 8);
            *reinterpret_cast<uint2*>(smem + S_A0 + SW(off)) = val;
        }

        float acc[2][13][4];
        #pragma unroll
        for (int j = 0; j < 2; ++j)
            #pragma unroll
            for (int b = 0; b < 13; ++b)
                #pragma unroll
                for (int k = 0; k < 4; ++k) acc[j][b][k] = 0.0f;

        // ---- main K loop (one barrier per chunk) ----
        for (int c = 0; c < NCHUNK; ++c) {
            const uint32_t sA = (c & 1) ? S_A1 : S_A0;
            const uint32_t sB = (c & 1) ? S_B1 : S_B0;
            asm volatile("cp.async.wait_group 0;" ::: "memory");
            __syncthreads();                                // buf c ready; c-1 done

            if (c + 1 < NCHUNK) {                           // prefetch c+1
                const float* xbn = xb0 + (c + 1) * KC;
                #pragma unroll
                for (int r = 0; r < 8; ++r)
                    av[r] = *reinterpret_cast<const float4*>(xbn + (size_t)r * 16 * Dk);
                const uint32_t sBn = (c & 1) ? S_B0 : S_B1;
                const __half* ws = wsrc + (c + 1) * KC;
                for (int i = tid; i < BN * 8; i += NT) {
                    const int row = i >> 3, c16 = i & 7;
                    const uint32_t off = (uint32_t)(row * 128 + c16 * 16);
                    cp16(smb + sBn + SW(off), ws + (size_t)row * Dk + c16 * 8);
                }
                asm volatile("cp.async.commit_group;" ::: "memory");
            }

            // compute chunk c
            #pragma unroll
            for (int ks = 0; ks < 4; ++ks) {
                uint32_t a[2][4];
                #pragma unroll
                for (int j = 0; j < 2; ++j) {
                    const uint32_t off = (uint32_t)((warpM * 32 + j * 16 + (lane & 15)) * 128
                                         + ks * 32 + ((lane >> 4) << 4));
                    ldsm_x4(a[j], smb + sA + SW(off));
                }
                #pragma unroll
                for (int p = 0; p < 6; ++p) {
                    uint32_t bq[4];
                    const uint32_t rowb = (uint32_t)(warpN * 104 + p * 16 + (lane & 7)
                                         + ((lane >> 4) << 3));
                    const uint32_t off = rowb * 128 + ks * 32 + (((lane >> 3) & 1) << 4);
                    ldsm_x4(bq, smb + sB + SW(off));
                    mma16816(acc[0][2 * p],     a[0], bq[0], bq[1]);
                    mma16816(acc[0][2 * p + 1], a[0], bq[2], bq[3]);
                    mma16816(acc[1][2 * p],     a[1], bq[0], bq[1]);
                    mma16816(acc[1][2 * p + 1], a[1], bq[2], bq[3]);
                }
                if (warpN == 0) {   // tail block 12 (cols 96..103 of warpN0 slice)
                    uint32_t b2[2];
                    const uint32_t rowb = (uint32_t)(96 + (lane & 7));
                    const uint32_t off = rowb * 128 + ks * 32 + (((lane >> 3) & 1) << 4);
                    ldsm_x2(b2, smb + sB + SW(off));
                    mma16816(acc[0][12], a[0], b2[0], b2[1]);
                    mma16816(acc[1][12], a[1], b2[0], b2[1]);
                }
            }

            if (c + 1 < NCHUNK) {
                // store A(c+1) into buffer last read at chunk c-1 (safe post-barrier)
                const uint32_t sAn = (c & 1) ? S_A0 : S_A1;
                #pragma unroll
                for (int r = 0; r < 8; ++r) {
                    __half2 p0 = __float22half2_rn(make_float2(av[r].x, av[r].y));
                    __half2 p1 = __float22half2_rn(make_float2(av[r].z, av[r].w));
                    uint2 val;
                    val.x = *reinterpret_cast<uint32_t*>(&p0);
                    val.y = *reinterpret_cast<uint32_t*>(&p1);
                    const uint32_t off = (uint32_t)((rb + 16 * r) * 128 + f4 * 8);
                    *reinterpret_cast<uint2*>(smem + sAn + SW(off)) = val;
                }
            }
        }

        // ---- per-pass epilogue: fold trees into wac ----
        #pragma unroll
        for (int j = 0; j < 2; ++j) {
            #pragma unroll
            for (int b = 0; b < 13; ++b) {
                if (b < nblk) {
                    const int cg = g * BN + warpN * 104 + b * 8 + q * 2;
                    const float bias0 = bias_sm[cg], bias1 = bias_sm[cg + 1];
                    const float fwv = fw_sm[cg >> 2];
                    #pragma unroll
                    for (int h = 0; h < 2; ++h) {
                        const float s0 = acc[j][b][2 * h]     + bias0;
                        const float s1 = acc[j][b][2 * h + 1] + bias1;
                        const float sp = s0 + s1;
                        const float S  = sp + __shfl_xor_sync(0xffffffffu, sp, 1);
                        const float wS = fwv * S;
                        wac[j * 2 + h][0] = fmaf(wS, sig_t(s0), wac[j * 2 + h][0]);
                        wac[j * 2 + h][1] = fmaf(wS, sig_t(s1), wac[j * 2 + h][1]);
                    }
                }
            }
        }
        // pass boundary: next prologue writes A0/B0, last read at chunk 14 —
        // every warp passed the chunk-15 barrier before reaching here. Safe.
    }

    // ---- combine tree halves within warp (lanes q ^ 2) ----
    #pragma unroll
    for (int s = 0; s < 4; ++s) {
        wac[s][0] += __shfl_xor_sync(0xffffffffu, wac[s][0], 2);
        wac[s][1] += __shfl_xor_sync(0xffffffffu, wac[s][1], 2);
    }

    // ---- cross-warpN reduction ----
    float* red = reinterpret_cast<float*>(smem + S_RED);
    if (warpN == 1 && q < 2) {
        #pragma unroll
        for (int s = 0; s < 4; ++s) {
            const int rl = warpM * 32 + (s >> 1) * 16 + (s & 1) * 8 + rq;
            red[rl * 4 + q * 2]     = wac[s][0];
            red[rl * 4 + q * 2 + 1] = wac[s][1];
        }
    }
    __syncthreads();

    if (ng == 2) {
        // 2-pass CTA holds the full tree sum: FC + direct store
        if (warpN == 0) {
            const float w00 = fw_sm[100], w01 = fw_sm[101], w02 = fw_sm[102], w03 = fw_sm[103];
            const float w10 = fw_sm[104], w11 = fw_sm[105], w12 = fw_sm[106], w13 = fw_sm[107];
            const float c0  = fw_sm[108], c1  = fw_sm[109];
            #pragma unroll
            for (int s = 0; s < 4; ++s) {
                const int rl = warpM * 32 + (s >> 1) * 16 + (s & 1) * 8 + rq;
                const int ki = (q & 1) * 2;
                const float v0 = wac[s][0] + red[rl * 4 + ki];
                const float v1 = wac[s][1] + red[rl * 4 + ki + 1];
                const float u0 = __shfl_xor_sync(0xffffffffu, v0, 1);
                const float u1 = __shfl_xor_sync(0xffffffffu, v1, 1);
                if (q == 0) {
                    float2 o;
                    o.x = c0 + v0 * w00 + v1 * w01 + u0 * w02 + u1 * w03;
                    o.y = c1 + v0 * w10 + v1 * w11 + u0 * w12 + u1 * w13;
                    *reinterpret_cast<float2*>(out + 2 * (row0 + rl)) = o;
                }
            }
        }
    } else {
        // single-pass CTA: write partial weighted[b, 0..3] for its group
        if (warpN == 0 && q < 2) {
            #pragma unroll
            for (int s = 0; s < 4; ++s) {
                const int rl = warpM * 32 + (s >> 1) * 16 + (s & 1) * 8 + rq;
                float2 v;
                v.x = wac[s][0] + red[rl * 4 + q * 2];
                v.y = wac[s][1] + red[rl * 4 + q * 2 + 1];
                *reinterpret_cast<float2*>(&g_part[g0][row0 + rl][q * 2]) = v;
            }
        }
    }
}

// ---------------- kernel 3: combine groups + FC for rows >= ROWSPLIT --------
__global__ void xgb_final(const float* __restrict__ fcw, const float* __restrict__ fcb,
                          float* __restrict__ out) {
    const int r = ROWSPLIT + blockIdx.x * 256 + threadIdx.x;
    float4 a = *reinterpret_cast<const float4*>(&g_part[0][r][0]);
    float4 b = *reinterpret_cast<const float4*>(&g_part[1][r][0]);
    const float w0 = a.x + b.x, w1 = a.y + b.y, w2 = a.z + b.z, w3 = a.w + b.w;
    float2 o;
    o.x = fcb[0] + w0 * fcw[0] + w1 * fcw[1] + w2 * fcw[2] + w3 * fcw[3];
    o.y = fcb[1] + w0 * fcw[4] + w1 * fcw[5] + w2 * fcw[6] + w3 * fcw[7];
    *reinterpret_cast<float2*>(out + 2 * r) = o;
}

// ---------------- launch ----------------------------------------------------
extern "C" void kernel_launch(void* const* d_in, const int* in_sizes, int n_in,
                              void* d_out, int out_size) {
    const float* x   = (const float*)d_in[0];
    const float* W1  = (const float*)d_in[1];
    const float* b1  = (const float*)d_in[2];
    const float* fw  = (const float*)d_in[3];
    const float* fcw = (const float*)d_in[4];
    const float* fcb = (const float*)d_in[5];
    float* out = (float*)d_out;

    cudaFuncSetAttribute(xgb_main, cudaFuncAttributeMaxDynamicSharedMemorySize, S_TOTAL);

    xgb_conv_w<<<400, 256>>>(W1);
    // 444 CTAs: 68 double-units (tiles 0..67, launched first) + 376 single-units
    xgb_main<<<NDBL + (256 - NDBL) * 2, NT, S_TOTAL>>>(x, b1, fw, fcw, fcb, out);
    xgb_final<<<(BTOT - ROWSPLIT) / 256, 256>>>(fcw, fcb, out);
}

// round 14
// speedup vs baseline: 1.0155x; 1.0155x over previous
#include <cuda_runtime.h>
#include <cuda_fp16.h>
#include <cstdint>

// ============================================================================
// DifferentiableXGB — base-arch (compute_103), consolidated best-config.
// GEMM: split[B,400] = x[32768,1024] @ W1^T via mma.sync m16n8k16 f32.f16.
// Composition of independently validated wins:
//   - R3 grid/pipeline: 256 CTAs (one per 128-row x tile), NT=256,
//     warpM 0..3 x warpN 0..1, two tree-group passes, reg-staged x,
//     double-buffered A/B, one barrier per chunk.
//   - fp16 inputs (R11/R12): rel_err 1.6e-5 (8x better than bf16), same speed.
//   - BN=200 exact (R13 kernel): no padded columns; warpN0 owns 104 cols
//     (13 n8-blocks incl. x2 tail), warpN1 owns 96 (12 blocks).
// Fused tree epilogue + FC in-kernel. 2 kernels total (conv_w + main).
// Measured platform context: legacy mma.sync ~15-16 cyc/HMMA/SMSP regardless
// of occupancy/accum-type; tcgen05 blocked by compute_103 PTX target.
// ============================================================================

static constexpr int BTOT  = 32768;
static constexpr int Dk    = 1024;
static constexpr int NCOL  = 400;
static constexpr int BN    = 200;    // cols per pass (50 trees) — exact
static constexpr int BM    = 128;
static constexpr int KC    = 64;     // k-chunk: 64 fp16 = 128B row (SW128)
static constexpr int NCHUNK= 16;
static constexpr int NT    = 256;

// smem byte offsets
static constexpr int S_BIAS = 0;        // 400 f = 1600 B
static constexpr int S_FW   = 1600;     // 100 fw + 8 fcw + 2 fcb
static constexpr int S_RED  = 2048;     // 512 f
static constexpr int S_A0   = 8192;     // 128*128B = 16384
static constexpr int S_A1   = 24576;
static constexpr int S_B0   = 40960;    // 200*128B = 25600
static constexpr int S_B1   = 66560;
static constexpr int S_TOTAL= 92160;

#define SW(o) ((o) ^ (((o) >> 3) & 0x70))

__device__ __align__(16) __half g_Wh[NCOL * Dk];   // 800 KB fp16 W scratch

// ---------------- asm helpers (all base-arch) ----------------
__device__ __forceinline__ uint32_t smem_u32(const void* p) {
    uint32_t a;
    asm("{ .reg .u64 t; cvta.to.shared.u64 t, %1; cvt.u32.u64 %0, t; }" : "=r"(a) : "l"(p));
    return a;
}
__device__ __forceinline__ void ldsm_x4(uint32_t (&r)[4], uint32_t addr) {
    asm volatile("ldmatrix.sync.aligned.m8n8.x4.shared.b16 {%0,%1,%2,%3}, [%4];"
                 : "=r"(r[0]), "=r"(r[1]), "=r"(r[2]), "=r"(r[3]) : "r"(addr));
}
__device__ __forceinline__ void ldsm_x2(uint32_t (&r)[2], uint32_t addr) {
    asm volatile("ldmatrix.sync.aligned.m8n8.x2.shared.b16 {%0,%1}, [%2];"
                 : "=r"(r[0]), "=r"(r[1]) : "r"(addr));
}
__device__ __forceinline__ void mma16816(float (&c)[4], const uint32_t (&a)[4],
                                         uint32_t b0, uint32_t b1) {
    asm volatile("mma.sync.aligned.m16n8k16.row.col.f32.f16.f16.f32 "
                 "{%0,%1,%2,%3}, {%4,%5,%6,%7}, {%8,%9}, {%0,%1,%2,%3};"
                 : "+f"(c[0]), "+f"(c[1]), "+f"(c[2]), "+f"(c[3])
                 : "r"(a[0]), "r"(a[1]), "r"(a[2]), "r"(a[3]), "r"(b0), "r"(b1));
}
__device__ __forceinline__ void cp16(uint32_t dst, const void* src) {
    asm volatile("cp.async.cg.shared.global [%0], [%1], 16;" :: "r"(dst), "l"(src));
}
__device__ __forceinline__ float sig_t(float v) {   // sigmoid via 1 MUFU (tanh)
    float t;
    asm("tanh.approx.f32 %0, %1;" : "=f"(t) : "f"(v * 0.5f));
    return fmaf(t, 0.5f, 0.5f);
}

// ---------------- kernel 1: W1 fp32 -> fp16 (exact 400 rows) ----------------
__global__ void xgb_conv_w(const float* __restrict__ W1) {
    int idx = blockIdx.x * 256 + threadIdx.x;      // 400*256 = 102400 uint2
    float4 v = reinterpret_cast<const float4*>(W1)[idx];
    __half2 p0 = __float22half2_rn(make_float2(v.x, v.y));
    __half2 p1 = __float22half2_rn(make_float2(v.z, v.w));
    uint2 o;
    o.x = *reinterpret_cast<uint32_t*>(&p0);
    o.y = *reinterpret_cast<uint32_t*>(&p1);
    reinterpret_cast<uint2*>(g_Wh)[idx] = o;
}

// ---------------- kernel 2: GEMM + fused tree epilogue + FC -----------------
__global__ void __launch_bounds__(NT, 1)
xgb_main(const float* __restrict__ x, const float* __restrict__ b1,
         const float* __restrict__ fw, const float* __restrict__ fcw,
         const float* __restrict__ fcb, float* __restrict__ out) {
    extern __shared__ char smem[];
    const uint32_t smb = smem_u32(smem);
    const int tid  = threadIdx.x;
    const int lane = tid & 31;
    const int wid  = tid >> 5;
    const int warpM = wid & 3, warpN = wid >> 2;   // 4 x 2
    const int row0  = blockIdx.x * BM;
    const int q  = lane & 3;     // col quad within n8 block
    const int rq = lane >> 2;    // row within 8
    // warpN0: 13 n8-blocks (104 cols incl. x2 tail); warpN1: 12 blocks (96 cols)
    const int nblk = (warpN == 0) ? 13 : 12;

    // constants to smem
    float* bias_sm = reinterpret_cast<float*>(smem + S_BIAS);
    float* fw_sm   = reinterpret_cast<float*>(smem + S_FW);
    for (int i = tid; i < NCOL; i += NT) bias_sm[i] = b1[i];
    if (tid < 100) fw_sm[tid] = fw[tid];
    if (tid < 8)   fw_sm[100 + tid] = fcw[tid];
    if (tid < 2)   fw_sm[108 + tid] = fcb[tid];

    float wac[4][2] = {{0.f,0.f},{0.f,0.f},{0.f,0.f},{0.f,0.f}};

    for (int g = 0; g < 2; ++g) {
        const __half* wsrc = g_Wh + (size_t)g * BN * Dk;

        // ---- prologue: chunk 0 ----
        float4 av[8];
        const int f4 = tid & 15, rb = tid >> 4;
        const float* xb0 = x + (size_t)(row0 + rb) * Dk + f4 * 4;
        #pragma unroll
        for (int r = 0; r < 8; ++r)
            av[r] = *reinterpret_cast<const float4*>(xb0 + (size_t)r * 16 * Dk);
        for (int i = tid; i < BN * 8; i += NT) {           // B(0) -> buf0
            const int row = i >> 3, c16 = i & 7;
            const uint32_t off = (uint32_t)(row * 128 + c16 * 16);
            cp16(smb + S_B0 + SW(off), wsrc + (size_t)row * Dk + c16 * 8);
        }
        asm volatile("cp.async.commit_group;" ::: "memory");
        #pragma unroll
        for (int r = 0; r < 8; ++r) {                      // A(0) -> buf0
            __half2 p0 = __float22half2_rn(make_float2(av[r].x, av[r].y));
            __half2 p1 = __float22half2_rn(make_float2(av[r].z, av[r].w));
            uint2 val;
            val.x = *reinterpret_cast<uint32_t*>(&p0);
            val.y = *reinterpret_cast<uint32_t*>(&p1);
            const uint32_t off = (uint32_t)((rb + 16 * r) * 128 + f4 * 8);
            *reinterpret_cast<uint2*>(smem + S_A0 + SW(off)) = val;
        }

        float acc[2][13][4];
        #pragma unroll
        for (int j = 0; j < 2; ++j)
            #pragma unroll
            for (int b = 0; b < 13; ++b)
                #pragma unroll
                for (int k = 0; k < 4; ++k) acc[j][b][k] = 0.0f;

        // ---- main K loop (one barrier per chunk) ----
        for (int c = 0; c < NCHUNK; ++c) {
            const uint32_t sA = (c & 1) ? S_A1 : S_A0;
            const uint32_t sB = (c & 1) ? S_B1 : S_B0;
            asm volatile("cp.async.wait_group 0;" ::: "memory");
            __syncthreads();                                // buf c ready; c-1 done

            if (c + 1 < NCHUNK) {                           // prefetch c+1
                const float* xbn = xb0 + (c + 1) * KC;
                #pragma unroll
                for (int r = 0; r < 8; ++r)
                    av[r] = *reinterpret_cast<const float4*>(xbn + (size_t)r * 16 * Dk);
                const uint32_t sBn = (c & 1) ? S_B0 : S_B1;
                const __half* ws = wsrc + (c + 1) * KC;
                for (int i = tid; i < BN * 8; i += NT) {
                    const int row = i >> 3, c16 = i & 7;
                    const uint32_t off = (uint32_t)(row * 128 + c16 * 16);
                    cp16(smb + sBn + SW(off), ws + (size_t)row * Dk + c16 * 8);
                }
                asm volatile("cp.async.commit_group;" ::: "memory");
            }

            // compute chunk c
            #pragma unroll
            for (int ks = 0; ks < 4; ++ks) {
                uint32_t a[2][4];
                #pragma unroll
                for (int j = 0; j < 2; ++j) {
                    const uint32_t off = (uint32_t)((warpM * 32 + j * 16 + (lane & 15)) * 128
                                         + ks * 32 + ((lane >> 4) << 4));
                    ldsm_x4(a[j], smb + sA + SW(off));
                }
                #pragma unroll
                for (int p = 0; p < 6; ++p) {
                    uint32_t bq[4];
                    const uint32_t rowb = (uint32_t)(warpN * 104 + p * 16 + (lane & 7)
                                         + ((lane >> 4) << 3));
                    const uint32_t off = rowb * 128 + ks * 32 + (((lane >> 3) & 1) << 4);
                    ldsm_x4(bq, smb + sB + SW(off));
                    mma16816(acc[0][2 * p],     a[0], bq[0], bq[1]);
                    mma16816(acc[0][2 * p + 1], a[0], bq[2], bq[3]);
                    mma16816(acc[1][2 * p],     a[1], bq[0], bq[1]);
                    mma16816(acc[1][2 * p + 1], a[1], bq[2], bq[3]);
                }
                if (warpN == 0) {   // tail block 12 (cols 96..103 of warpN0 slice)
                    uint32_t b2[2];
                    const uint32_t rowb = (uint32_t)(96 + (lane & 7));
                    const uint32_t off = rowb * 128 + ks * 32 + (((lane >> 3) & 1) << 4);
                    ldsm_x2(b2, smb + sB + SW(off));
                    mma16816(acc[0][12], a[0], b2[0], b2[1]);
                    mma16816(acc[1][12], a[1], b2[0], b2[1]);
                }
            }

            if (c + 1 < NCHUNK) {
                // store A(c+1) into buffer last read at chunk c-1 — safe:
                // every warp passed this chunk's barrier, so compute(c-1) is done.
                const uint32_t sAn = (c & 1) ? S_A0 : S_A1;
                #pragma unroll
                for (int r = 0; r < 8; ++r) {
                    __half2 p0 = __float22half2_rn(make_float2(av[r].x, av[r].y));
                    __half2 p1 = __float22half2_rn(make_float2(av[r].z, av[r].w));
                    uint2 val;
                    val.x = *reinterpret_cast<uint32_t*>(&p0);
                    val.y = *reinterpret_cast<uint32_t*>(&p1);
                    const uint32_t off = (uint32_t)((rb + 16 * r) * 128 + f4 * 8);
                    *reinterpret_cast<uint2*>(smem + sAn + SW(off)) = val;
                }
            }
        }

        // ---- per-pass epilogue: fold trees into wac ----
        #pragma unroll
        for (int j = 0; j < 2; ++j) {
            #pragma unroll
            for (int b = 0; b < 13; ++b) {
                if (b < nblk) {
                    const int cg = g * BN + warpN * 104 + b * 8 + q * 2;
                    const float bias0 = bias_sm[cg], bias1 = bias_sm[cg + 1];
                    const float fwv = fw_sm[cg >> 2];
                    #pragma unroll
                    for (int h = 0; h < 2; ++h) {
                        const float s0 = acc[j][b][2 * h]     + bias0;
                        const float s1 = acc[j][b][2 * h + 1] + bias1;
                        const float sp = s0 + s1;
                        const float S  = sp + __shfl_xor_sync(0xffffffffu, sp, 1);
                        const float wS = fwv * S;
                        wac[j * 2 + h][0] = fmaf(wS, sig_t(s0), wac[j * 2 + h][0]);
                        wac[j * 2 + h][1] = fmaf(wS, sig_t(s1), wac[j * 2 + h][1]);
                    }
                }
            }
        }
        // pass boundary: next prologue writes A0/B0, last read at chunk 14 —
        // every warp passed the chunk-15 barrier before reaching here. Safe.
    }

    // ---- combine tree halves within warp (lanes q ^ 2) ----
    #pragma unroll
    for (int s = 0; s < 4; ++s) {
        wac[s][0] += __shfl_xor_sync(0xffffffffu, wac[s][0], 2);
        wac[s][1] += __shfl_xor_sync(0xffffffffu, wac[s][1], 2);
    }

    // ---- cross-warpN reduction + FC + store ----
    float* red = reinterpret_cast<float*>(smem + S_RED);
    if (warpN == 1 && q < 2) {
        #pragma unroll
        for (int s = 0; s < 4; ++s) {
            const int rl = warpM * 32 + (s >> 1) * 16 + (s & 1) * 8 + rq;
            red[rl * 4 + q * 2]     = wac[s][0];
            red[rl * 4 + q * 2 + 1] = wac[s][1];
        }
    }
    __syncthreads();
    if (warpN == 0) {
        const float w00 = fw_sm[100], w01 = fw_sm[101], w02 = fw_sm[102], w03 = fw_sm[103];
        const float w10 = fw_sm[104], w11 = fw_sm[105], w12 = fw_sm[106], w13 = fw_sm[107];
        const float c0  = fw_sm[108], c1  = fw_sm[109];
        #pragma unroll
        for (int s = 0; s < 4; ++s) {
            const int rl = warpM * 32 + (s >> 1) * 16 + (s & 1) * 8 + rq;
            const int ki = (q & 1) * 2;
            const float v0 = wac[s][0] + red[rl * 4 + ki];
            const float v1 = wac[s][1] + red[rl * 4 + ki + 1];
            // partner lane (q^1) holds the other k-pair
            const float u0 = __shfl_xor_sync(0xffffffffu, v0, 1);
            const float u1 = __shfl_xor_sync(0xffffffffu, v1, 1);
            if (q == 0) {
                // k0=v0 k1=v1 k2=u0 k3=u1
                float2 o;
                o.x = c0 + v0 * w00 + v1 * w01 + u0 * w02 + u1 * w03;
                o.y = c1 + v0 * w10 + v1 * w11 + u0 * w12 + u1 * w13;
                *reinterpret_cast<float2*>(out + 2 * (row0 + rl)) = o;
            }
        }
    }
}

// ---------------- launch ----------------------------------------------------
extern "C" void kernel_launch(void* const* d_in, const int* in_sizes, int n_in,
                              void* d_out, int out_size) {
    const float* x   = (const float*)d_in[0];
    const float* W1  = (const float*)d_in[1];
    const float* b1  = (const float*)d_in[2];
    const float* fw  = (const float*)d_in[3];
    const float* fcw = (const float*)d_in[4];
    const float* fcb = (const float*)d_in[5];
    float* out = (float*)d_out;

    cudaFuncSetAttribute(xgb_main, cudaFuncAttributeMaxDynamicSharedMemorySize, S_TOTAL);

    xgb_conv_w<<<400, 256>>>(W1);
    xgb_main<<<BTOT / BM, NT, S_TOTAL>>>(x, b1, fw, fcw, fcb, out);
}

// round 15
// speedup vs baseline: 1.0967x; 1.0799x over previous
#include <cuda_runtime.h>
#include <cuda_fp16.h>
#include <cstdint>

// ============================================================================
// DifferentiableXGB — base-arch (compute_103), consolidated measured-best.
// GEMM: split[B,416pad] = x[32768,1024] @ W1^T via mma.sync m16n8k16 f32.f16.
// Structure = R2 (fastest measured main ~101us): 512 CTAs = 256 x-tiles x 2
// tree-groups, one group per CTA (fine granularity -> best wave balance),
// NT=256 (warpM 0..3 x warpN 0..1, j=2, acc=104), BN=208 symmetric (the
// asymmetric exact-200 split measured 6us slower), reg-staged x, double-
// buffered A/B, one barrier per chunk. fp16 inputs (rel_err 1.6e-5).
// conv_w upgraded to MLP=4 (latency-bound at MLP=1 before).
// 3 kernels: conv_w + main + final(FC).
// Platform notes (measured): legacy mma.sync ~15-16cyc issue/HMMA/SMSP at any
// occupancy; tcgen05 blocked by compute_103 PTX target; int8 IMMA slower.
// ============================================================================

static constexpr int BTOT  = 32768;
static constexpr int Dk    = 1024;
static constexpr int NPAD  = 416;    // 400 cols padded (pad trees have fw=0)
static constexpr int BN    = 208;    // cols per group-CTA (52 trees)
static constexpr int BM    = 128;
static constexpr int KC    = 64;     // k-chunk: 64 fp16 = 128B row (SW128)
static constexpr int NCHUNK= 16;
static constexpr int NT    = 256;

// smem byte offsets
static constexpr int S_BIAS = 0;        // 416 f
static constexpr int S_FW   = 1664;     // 104 f
static constexpr int S_RED  = 4096;     // 128*4 f
static constexpr int S_A0   = 8192;     // 128*128B = 16384
static constexpr int S_A1   = 24576;
static constexpr int S_B0   = 40960;    // 208*128B = 26624
static constexpr int S_B1   = 67584;
static constexpr int S_TOTAL= 94208;

#define SW(o) ((o) ^ (((o) >> 3) & 0x70))

__device__ __align__(16) __half g_Wh[NPAD * Dk];   // 852 KB fp16 W scratch
__device__ float g_part[2][BTOT][4];                // 1 MB partials

// ---------------- asm helpers (all base-arch) ----------------
__device__ __forceinline__ uint32_t smem_u32(const void* p) {
    uint32_t a;
    asm("{ .reg .u64 t; cvta.to.shared.u64 t, %1; cvt.u32.u64 %0, t; }" : "=r"(a) : "l"(p));
    return a;
}
__device__ __forceinline__ void ldsm_x4(uint32_t (&r)[4], uint32_t addr) {
    asm volatile("ldmatrix.sync.aligned.m8n8.x4.shared.b16 {%0,%1,%2,%3}, [%4];"
                 : "=r"(r[0]), "=r"(r[1]), "=r"(r[2]), "=r"(r[3]) : "r"(addr));
}
__device__ __forceinline__ void ldsm_x2(uint32_t (&r)[2], uint32_t addr) {
    asm volatile("ldmatrix.sync.aligned.m8n8.x2.shared.b16 {%0,%1}, [%2];"
                 : "=r"(r[0]), "=r"(r[1]) : "r"(addr));
}
__device__ __forceinline__ void mma16816(float (&c)[4], const uint32_t (&a)[4],
                                         uint32_t b0, uint32_t b1) {
    asm volatile("mma.sync.aligned.m16n8k16.row.col.f32.f16.f16.f32 "
                 "{%0,%1,%2,%3}, {%4,%5,%6,%7}, {%8,%9}, {%0,%1,%2,%3};"
                 : "+f"(c[0]), "+f"(c[1]), "+f"(c[2]), "+f"(c[3])
                 : "r"(a[0]), "r"(a[1]), "r"(a[2]), "r"(a[3]), "r"(b0), "r"(b1));
}
__device__ __forceinline__ void cp16(uint32_t dst, const void* src) {
    asm volatile("cp.async.cg.shared.global [%0], [%1], 16;" :: "r"(dst), "l"(src));
}
__device__ __forceinline__ float sig_t(float v) {   // sigmoid via 1 MUFU (tanh)
    float t;
    asm("tanh.approx.f32 %0, %1;" : "=f"(t) : "f"(v * 0.5f));
    return fmaf(t, 0.5f, 0.5f);
}

// ---------------- kernel 1: W1 fp32 -> fp16, MLP=4 (padded to 416 rows) -----
__global__ void xgb_conv_w(const float* __restrict__ W1) {
    // 100 blocks x 256 threads x 4 float4 = 102400 float4 (exactly 400*1024/4)
    const int base = blockIdx.x * 1024 + threadIdx.x;
    float4 v[4];
    #pragma unroll
    for (int k = 0; k < 4; ++k)
        v[k] = reinterpret_cast<const float4*>(W1)[base + k * 256];
    #pragma unroll
    for (int k = 0; k < 4; ++k) {
        __half2 p0 = __float22half2_rn(make_float2(v[k].x, v[k].y));
        __half2 p1 = __float22half2_rn(make_float2(v[k].z, v[k].w));
        uint2 o;
        o.x = *reinterpret_cast<uint32_t*>(&p0);
        o.y = *reinterpret_cast<uint32_t*>(&p1);
        reinterpret_cast<uint2*>(g_Wh)[base + k * 256] = o;
    }
}
// zero-fill padded W rows 400..415 (once; pad trees also have fw=0)
__global__ void xgb_pad_w() {
    const int idx = blockIdx.x * 256 + threadIdx.x;    // 16*1024/4 = 4096 uint2
    reinterpret_cast<uint2*>(g_Wh + 400 * Dk)[idx] = make_uint2(0u, 0u);
}

// ---------------- kernel 2: GEMM + fused tree epilogue ----------------------
__global__ void __launch_bounds__(NT, 1)
xgb_main(const float* __restrict__ x, const float* __restrict__ b1,
         const float* __restrict__ fw) {
    extern __shared__ char smem[];
    const uint32_t smb = smem_u32(smem);
    const int tid  = threadIdx.x;
    const int lane = tid & 31;
    const int wid  = tid >> 5;
    const int warpM = wid & 3, warpN = wid >> 2;
    const int g     = blockIdx.x & 1;
    const int row0  = (blockIdx.x >> 1) * BM;
    const int q  = lane & 3;
    const int rq = lane >> 2;

    // constants to smem
    float* bias_sm = reinterpret_cast<float*>(smem + S_BIAS);
    float* fw_sm   = reinterpret_cast<float*>(smem + S_FW);
    for (int i = tid; i < NPAD; i += NT) bias_sm[i] = (i < 400) ? b1[i] : 0.0f;
    if (tid < 104) fw_sm[tid] = (tid < 100) ? fw[tid] : 0.0f;

    const __half* wsrc = g_Wh + (size_t)g * BN * Dk;

    // ---- prologue: chunk 0 ----
    float4 av[8];
    const int f4 = tid & 15, rb = tid >> 4;
    const float* xb0 = x + (size_t)(row0 + rb) * Dk + f4 * 4;
    #pragma unroll
    for (int r = 0; r < 8; ++r)
        av[r] = *reinterpret_cast<const float4*>(xb0 + (size_t)r * 16 * Dk);
    for (int i = tid; i < BN * 8; i += NT) {           // B(0) -> buf0
        const int row = i >> 3, c16 = i & 7;
        const uint32_t off = (uint32_t)(row * 128 + c16 * 16);
        cp16(smb + S_B0 + SW(off), wsrc + (size_t)row * Dk + c16 * 8);
    }
    asm volatile("cp.async.commit_group;" ::: "memory");
    #pragma unroll
    for (int r = 0; r < 8; ++r) {                      // A(0) -> buf0
        __half2 p0 = __float22half2_rn(make_float2(av[r].x, av[r].y));
        __half2 p1 = __float22half2_rn(make_float2(av[r].z, av[r].w));
        uint2 val;
        val.x = *reinterpret_cast<uint32_t*>(&p0);
        val.y = *reinterpret_cast<uint32_t*>(&p1);
        const uint32_t off = (uint32_t)((rb + 16 * r) * 128 + f4 * 8);
        *reinterpret_cast<uint2*>(smem + S_A0 + SW(off)) = val;
    }

    float acc[2][13][4];
    #pragma unroll
    for (int j = 0; j < 2; ++j)
        #pragma unroll
        for (int b = 0; b < 13; ++b)
            #pragma unroll
            for (int k = 0; k < 4; ++k) acc[j][b][k] = 0.0f;

    // ---- main K loop (one barrier per chunk) ----
    for (int c = 0; c < NCHUNK; ++c) {
        const uint32_t sA = (c & 1) ? S_A1 : S_A0;
        const uint32_t sB = (c & 1) ? S_B1 : S_B0;
        asm volatile("cp.async.wait_group 0;" ::: "memory");
        __syncthreads();                                // buf c ready; c-1 done

        if (c + 1 < NCHUNK) {                           // prefetch c+1
            const float* xbn = xb0 + (c + 1) * KC;
            #pragma unroll
            for (int r = 0; r < 8; ++r)
                av[r] = *reinterpret_cast<const float4*>(xbn + (size_t)r * 16 * Dk);
            const uint32_t sBn = (c & 1) ? S_B0 : S_B1;
            const __half* ws = wsrc + (c + 1) * KC;
            for (int i = tid; i < BN * 8; i += NT) {
                const int row = i >> 3, c16 = i & 7;
                const uint32_t off = (uint32_t)(row * 128 + c16 * 16);
                cp16(smb + sBn + SW(off), ws + (size_t)row * Dk + c16 * 8);
            }
            asm volatile("cp.async.commit_group;" ::: "memory");
        }

        // compute chunk c
        #pragma unroll
        for (int ks = 0; ks < 4; ++ks) {
            uint32_t a[2][4];
            #pragma unroll
            for (int j = 0; j < 2; ++j) {
                const uint32_t off = (uint32_t)((warpM * 32 + j * 16 + (lane & 15)) * 128
                                     + ks * 32 + ((lane >> 4) << 4));
                ldsm_x4(a[j], smb + sA + SW(off));
            }
            #pragma unroll
            for (int p = 0; p < 6; ++p) {
                uint32_t bq[4];
                const uint32_t rowb = (uint32_t)(warpN * 104 + p * 16 + (lane & 7)
                                     + ((lane >> 4) << 3));
                const uint32_t off = rowb * 128 + ks * 32 + (((lane >> 3) & 1) << 4);
                ldsm_x4(bq, smb + sB + SW(off));
                mma16816(acc[0][2 * p],     a[0], bq[0], bq[1]);
                mma16816(acc[0][2 * p + 1], a[0], bq[2], bq[3]);
                mma16816(acc[1][2 * p],     a[1], bq[0], bq[1]);
                mma16816(acc[1][2 * p + 1], a[1], bq[2], bq[3]);
            }
            {   // last n8 block (12)
                uint32_t b2[2];
                const uint32_t rowb = (uint32_t)(warpN * 104 + 96 + (lane & 7));
                const uint32_t off = rowb * 128 + ks * 32 + (((lane >> 3) & 1) << 4);
                ldsm_x2(b2, smb + sB + SW(off));
                mma16816(acc[0][12], a[0], b2[0], b2[1]);
                mma16816(acc[1][12], a[1], b2[0], b2[1]);
            }
        }

        if (c + 1 < NCHUNK) {
            // store A(c+1) into buffer last read at chunk c-1 — safe post-barrier
            const uint32_t sAn = (c & 1) ? S_A0 : S_A1;
            #pragma unroll
            for (int r = 0; r < 8; ++r) {
                __half2 p0 = __float22half2_rn(make_float2(av[r].x, av[r].y));
                __half2 p1 = __float22half2_rn(make_float2(av[r].z, av[r].w));
                uint2 val;
                val.x = *reinterpret_cast<uint32_t*>(&p0);
                val.y = *reinterpret_cast<uint32_t*>(&p1);
                const uint32_t off = (uint32_t)((rb + 16 * r) * 128 + f4 * 8);
                *reinterpret_cast<uint2*>(smem + sAn + SW(off)) = val;
            }
        }
    }

    // ---- fused tree epilogue: trees -> weighted[row, 0..3] partials ----
    float wac[4][2] = {{0.f,0.f},{0.f,0.f},{0.f,0.f},{0.f,0.f}};
    #pragma unroll
    for (int j = 0; j < 2; ++j) {
        #pragma unroll
        for (int b = 0; b < 13; ++b) {
            const int cg = g * BN + warpN * 104 + b * 8 + q * 2;
            const float bias0 = bias_sm[cg], bias1 = bias_sm[cg + 1];
            const float fwv = fw_sm[cg >> 2];
            #pragma unroll
            for (int h = 0; h < 2; ++h) {
                const float s0 = acc[j][b][2 * h]     + bias0;
                const float s1 = acc[j][b][2 * h + 1] + bias1;
                const float sp = s0 + s1;
                const float S  = sp + __shfl_xor_sync(0xffffffffu, sp, 1);
                const float wS = fwv * S;
                wac[j * 2 + h][0] = fmaf(wS, sig_t(s0), wac[j * 2 + h][0]);
                wac[j * 2 + h][1] = fmaf(wS, sig_t(s1), wac[j * 2 + h][1]);
            }
        }
    }
    #pragma unroll
    for (int s = 0; s < 4; ++s) {        // combine tree halves (lanes q ^ 2)
        wac[s][0] += __shfl_xor_sync(0xffffffffu, wac[s][0], 2);
        wac[s][1] += __shfl_xor_sync(0xffffffffu, wac[s][1], 2);
    }
    float* red = reinterpret_cast<float*>(smem + S_RED);
    __syncthreads();
    if (warpN == 1 && q < 2) {
        #pragma unroll
        for (int s = 0; s < 4; ++s) {
            const int rl = warpM * 32 + (s >> 1) * 16 + (s & 1) * 8 + rq;
            red[rl * 4 + q * 2]     = wac[s][0];
            red[rl * 4 + q * 2 + 1] = wac[s][1];
        }
    }
    __syncthreads();
    if (warpN == 0 && q < 2) {
        #pragma unroll
        for (int s = 0; s < 4; ++s) {
            const int rl = warpM * 32 + (s >> 1) * 16 + (s & 1) * 8 + rq;
            float2 v;
            v.x = wac[s][0] + red[rl * 4 + q * 2];
            v.y = wac[s][1] + red[rl * 4 + q * 2 + 1];
            *reinterpret_cast<float2*>(&g_part[g][row0 + rl][q * 2]) = v;
        }
    }
}

// ---------------- kernel 3: combine groups + FC -----------------------------
__global__ void xgb_final(const float* __restrict__ fcw, const float* __restrict__ fcb,
                          float* __restrict__ out) {
    const int r = blockIdx.x * 256 + threadIdx.x;
    float4 a = *reinterpret_cast<const float4*>(&g_part[0][r][0]);
    float4 b = *reinterpret_cast<const float4*>(&g_part[1][r][0]);
    const float w0 = a.x + b.x, w1 = a.y + b.y, w2 = a.z + b.z, w3 = a.w + b.w;
    float2 o;
    o.x = fcb[0] + w0 * fcw[0] + w1 * fcw[1] + w2 * fcw[2] + w3 * fcw[3];
    o.y = fcb[1] + w0 * fcw[4] + w1 * fcw[5] + w2 * fcw[6] + w3 * fcw[7];
    *reinterpret_cast<float2*>(out + 2 * r) = o;
}

// ---------------- launch ----------------------------------------------------
extern "C" void kernel_launch(void* const* d_in, const int* in_sizes, int n_in,
                              void* d_out, int out_size) {
    const float* x   = (const float*)d_in[0];
    const float* W1  = (const float*)d_in[1];
    const float* b1  = (const float*)d_in[2];
    const float* fw  = (const float*)d_in[3];
    const float* fcw = (const float*)d_in[4];
    const float* fcb = (const float*)d_in[5];
    float* out = (float*)d_out;

    cudaFuncSetAttribute(xgb_main, cudaFuncAttributeMaxDynamicSharedMemorySize, S_TOTAL);

    xgb_pad_w<<<16, 256>>>();
    xgb_conv_w<<<100, 256>>>(W1);
    xgb_main<<<(BTOT / BM) * 2, NT, S_TOTAL>>>(x, b1, fw);
    xgb_final<<<BTOT / 256, 256>>>(fcw, fcb, out);
}

// round 16
// speedup vs baseline: 1.1003x; 1.0033x over previous
#include <cuda_runtime.h>
#include <cuda_fp16.h>
#include <cstdint>

// ============================================================================
// DifferentiableXGB — base-arch (compute_103), R15 + fused atomic FC.
// GEMM: split[B,416pad] = x[32768,1024] @ W1^T via mma.sync m16n8k16 f32.f16.
// Structure = R15 measured best: 512 CTAs = 256 x-tiles x 2 tree-groups,
// NT=256 (warpM 0..3 x warpN 0..1, j=2, acc=104), BN=208 symmetric,
// reg-staged x, double-buffered A/B, fp16 inputs (rel_err 1.6e-5).
// NEW: the final FC kernel is gone — FC is linear in the per-group partials,
// so each group-CTA atomicAdds its partial logits into out (g=0 adds fcb);
// out is zero-initialized by a tiny kernel. Exactly 2 adds per address onto
// 0 -> order-independent bit-exact result. 3 launches total.
// ============================================================================

static constexpr int BTOT  = 32768;
static constexpr int Dk    = 1024;
static constexpr int NPAD  = 416;    // 400 cols padded (pad trees have fw=0)
static constexpr int BN    = 208;    // cols per group-CTA (52 trees)
static constexpr int BM    = 128;
static constexpr int KC    = 64;     // k-chunk: 64 fp16 = 128B row (SW128)
static constexpr int NCHUNK= 16;
static constexpr int NT    = 256;

// smem byte offsets
static constexpr int S_BIAS = 0;        // 416 f
static constexpr int S_FW   = 1664;     // 104 fw + 8 fcw + 2 fcb
static constexpr int S_RED  = 4096;     // 128*4 f
static constexpr int S_A0   = 8192;     // 128*128B = 16384
static constexpr int S_A1   = 24576;
static constexpr int S_B0   = 40960;    // 208*128B = 26624
static constexpr int S_B1   = 67584;
static constexpr int S_TOTAL= 94208;

#define SW(o) ((o) ^ (((o) >> 3) & 0x70))

__device__ __align__(16) __half g_Wh[NPAD * Dk];   // 852 KB fp16 W scratch

// ---------------- asm helpers (all base-arch) ----------------
__device__ __forceinline__ uint32_t smem_u32(const void* p) {
    uint32_t a;
    asm("{ .reg .u64 t; cvta.to.shared.u64 t, %1; cvt.u32.u64 %0, t; }" : "=r"(a) : "l"(p));
    return a;
}
__device__ __forceinline__ void ldsm_x4(uint32_t (&r)[4], uint32_t addr) {
    asm volatile("ldmatrix.sync.aligned.m8n8.x4.shared.b16 {%0,%1,%2,%3}, [%4];"
                 : "=r"(r[0]), "=r"(r[1]), "=r"(r[2]), "=r"(r[3]) : "r"(addr));
}
__device__ __forceinline__ void ldsm_x2(uint32_t (&r)[2], uint32_t addr) {
    asm volatile("ldmatrix.sync.aligned.m8n8.x2.shared.b16 {%0,%1}, [%2];"
                 : "=r"(r[0]), "=r"(r[1]) : "r"(addr));
}
__device__ __forceinline__ void mma16816(float (&c)[4], const uint32_t (&a)[4],
                                         uint32_t b0, uint32_t b1) {
    asm volatile("mma.sync.aligned.m16n8k16.row.col.f32.f16.f16.f32 "
                 "{%0,%1,%2,%3}, {%4,%5,%6,%7}, {%8,%9}, {%0,%1,%2,%3};"
                 : "+f"(c[0]), "+f"(c[1]), "+f"(c[2]), "+f"(c[3])
                 : "r"(a[0]), "r"(a[1]), "r"(a[2]), "r"(a[3]), "r"(b0), "r"(b1));
}
__device__ __forceinline__ void cp16(uint32_t dst, const void* src) {
    asm volatile("cp.async.cg.shared.global [%0], [%1], 16;" :: "r"(dst), "l"(src));
}
__device__ __forceinline__ float sig_t(float v) {   // sigmoid via 1 MUFU (tanh)
    float t;
    asm("tanh.approx.f32 %0, %1;" : "=f"(t) : "f"(v * 0.5f));
    return fmaf(t, 0.5f, 0.5f);
}

// ---------------- kernel 0: zero-init out (poisoned 0xAA by harness) --------
__global__ void xgb_zero(float* __restrict__ out) {
    reinterpret_cast<float4*>(out)[blockIdx.x * 256 + threadIdx.x] =
        make_float4(0.f, 0.f, 0.f, 0.f);               // 64*256*4 = 65536 floats
}

// ---------------- kernel 1: W1 fp32 -> fp16 (MLP=4) + zero pad rows ---------
__global__ void xgb_conv_w(const float* __restrict__ W1) {
    if (blockIdx.x < 100) {
        // 100 blocks x 256 threads x 4 float4 = 102400 float4 = 400*1024 floats
        const int base = blockIdx.x * 1024 + threadIdx.x;
        float4 v[4];
        #pragma unroll
        for (int k = 0; k < 4; ++k)
            v[k] = reinterpret_cast<const float4*>(W1)[base + k * 256];
        #pragma unroll
        for (int k = 0; k < 4; ++k) {
            __half2 p0 = __float22half2_rn(make_float2(v[k].x, v[k].y));
            __half2 p1 = __float22half2_rn(make_float2(v[k].z, v[k].w));
            uint2 o;
            o.x = *reinterpret_cast<uint32_t*>(&p0);
            o.y = *reinterpret_cast<uint32_t*>(&p1);
            reinterpret_cast<uint2*>(g_Wh)[base + k * 256] = o;
        }
    } else {
        // 4 tail blocks zero rows 400..415: 16*1024 halves = 4096 uint2
        const int base = (blockIdx.x - 100) * 256 + threadIdx.x;   // 0..1023
        #pragma unroll
        for (int k = 0; k < 4; ++k)
            reinterpret_cast<uint2*>(g_Wh + 400 * Dk)[base + k * 1024] =
                make_uint2(0u, 0u);
    }
}

// ---------------- kernel 2: GEMM + fused tree epilogue + atomic FC ----------
__global__ void __launch_bounds__(NT, 1)
xgb_main(const float* __restrict__ x, const float* __restrict__ b1,
         const float* __restrict__ fw, const float* __restrict__ fcw,
         const float* __restrict__ fcb, float* __restrict__ out) {
    extern __shared__ char smem[];
    const uint32_t smb = smem_u32(smem);
    const int tid  = threadIdx.x;
    const int lane = tid & 31;
    const int wid  = tid >> 5;
    const int warpM = wid & 3, warpN = wid >> 2;
    const int g     = blockIdx.x & 1;
    const int row0  = (blockIdx.x >> 1) * BM;
    const int q  = lane & 3;
    const int rq = lane >> 2;

    // constants to smem
    float* bias_sm = reinterpret_cast<float*>(smem + S_BIAS);
    float* fw_sm   = reinterpret_cast<float*>(smem + S_FW);
    for (int i = tid; i < NPAD; i += NT) bias_sm[i] = (i < 400) ? b1[i] : 0.0f;
    if (tid < 104) fw_sm[tid] = (tid < 100) ? fw[tid] : 0.0f;
    if (tid < 8)   fw_sm[104 + tid] = fcw[tid];
    if (tid < 2)   fw_sm[112 + tid] = fcb[tid];

    const __half* wsrc = g_Wh + (size_t)g * BN * Dk;

    // ---- prologue: chunk 0 ----
    float4 av[8];
    const int f4 = tid & 15, rb = tid >> 4;
    const float* xb0 = x + (size_t)(row0 + rb) * Dk + f4 * 4;
    #pragma unroll
    for (int r = 0; r < 8; ++r)
        av[r] = *reinterpret_cast<const float4*>(xb0 + (size_t)r * 16 * Dk);
    for (int i = tid; i < BN * 8; i += NT) {           // B(0) -> buf0
        const int row = i >> 3, c16 = i & 7;
        const uint32_t off = (uint32_t)(row * 128 + c16 * 16);
        cp16(smb + S_B0 + SW(off), wsrc + (size_t)row * Dk + c16 * 8);
    }
    asm volatile("cp.async.commit_group;" ::: "memory");
    #pragma unroll
    for (int r = 0; r < 8; ++r) {                      // A(0) -> buf0
        __half2 p0 = __float22half2_rn(make_float2(av[r].x, av[r].y));
        __half2 p1 = __float22half2_rn(make_float2(av[r].z, av[r].w));
        uint2 val;
        val.x = *reinterpret_cast<uint32_t*>(&p0);
        val.y = *reinterpret_cast<uint32_t*>(&p1);
        const uint32_t off = (uint32_t)((rb + 16 * r) * 128 + f4 * 8);
        *reinterpret_cast<uint2*>(smem + S_A0 + SW(off)) = val;
    }

    float acc[2][13][4];
    #pragma unroll
    for (int j = 0; j < 2; ++j)
        #pragma unroll
        for (int b = 0; b < 13; ++b)
            #pragma unroll
            for (int k = 0; k < 4; ++k) acc[j][b][k] = 0.0f;

    // ---- main K loop (one barrier per chunk) ----
    for (int c = 0; c < NCHUNK; ++c) {
        const uint32_t sA = (c & 1) ? S_A1 : S_A0;
        const uint32_t sB = (c & 1) ? S_B1 : S_B0;
        asm volatile("cp.async.wait_group 0;" ::: "memory");
        __syncthreads();                                // buf c ready; c-1 done

        if (c + 1 < NCHUNK) {                           // prefetch c+1
            const float* xbn = xb0 + (c + 1) * KC;
            #pragma unroll
            for (int r = 0; r < 8; ++r)
                av[r] = *reinterpret_cast<const float4*>(xbn + (size_t)r * 16 * Dk);
            const uint32_t sBn = (c & 1) ? S_B0 : S_B1;
            const __half* ws = wsrc + (c + 1) * KC;
            for (int i = tid; i < BN * 8; i += NT) {
                const int row = i >> 3, c16 = i & 7;
                const uint32_t off = (uint32_t)(row * 128 + c16 * 16);
                cp16(smb + sBn + SW(off), ws + (size_t)row * Dk + c16 * 8);
            }
            asm volatile("cp.async.commit_group;" ::: "memory");
        }

        // compute chunk c
        #pragma unroll
        for (int ks = 0; ks < 4; ++ks) {
            uint32_t a[2][4];
            #pragma unroll
            for (int j = 0; j < 2; ++j) {
                const uint32_t off = (uint32_t)((warpM * 32 + j * 16 + (lane & 15)) * 128
                                     + ks * 32 + ((lane >> 4) << 4));
                ldsm_x4(a[j], smb + sA + SW(off));
            }
            #pragma unroll
            for (int p = 0; p < 6; ++p) {
                uint32_t bq[4];
                const uint32_t rowb = (uint32_t)(warpN * 104 + p * 16 + (lane & 7)
                                     + ((lane >> 4) << 3));
                const uint32_t off = rowb * 128 + ks * 32 + (((lane >> 3) & 1) << 4);
                ldsm_x4(bq, smb + sB + SW(off));
                mma16816(acc[0][2 * p],     a[0], bq[0], bq[1]);
                mma16816(acc[0][2 * p + 1], a[0], bq[2], bq[3]);
                mma16816(acc[1][2 * p],     a[1], bq[0], bq[1]);
                mma16816(acc[1][2 * p + 1], a[1], bq[2], bq[3]);
            }
            {   // last n8 block (12)
                uint32_t b2[2];
                const uint32_t rowb = (uint32_t)(warpN * 104 + 96 + (lane & 7));
                const uint32_t off = rowb * 128 + ks * 32 + (((lane >> 3) & 1) << 4);
                ldsm_x2(b2, smb + sB + SW(off));
                mma16816(acc[0][12], a[0], b2[0], b2[1]);
                mma16816(acc[1][12], a[1], b2[0], b2[1]);
            }
        }

        if (c + 1 < NCHUNK) {
            // store A(c+1) into buffer last read at chunk c-1 — safe post-barrier
            const uint32_t sAn = (c & 1) ? S_A0 : S_A1;
            #pragma unroll
            for (int r = 0; r < 8; ++r) {
                __half2 p0 = __float22half2_rn(make_float2(av[r].x, av[r].y));
                __half2 p1 = __float22half2_rn(make_float2(av[r].z, av[r].w));
                uint2 val;
                val.x = *reinterpret_cast<uint32_t*>(&p0);
                val.y = *reinterpret_cast<uint32_t*>(&p1);
                const uint32_t off = (uint32_t)((rb + 16 * r) * 128 + f4 * 8);
                *reinterpret_cast<uint2*>(smem + sAn + SW(off)) = val;
            }
        }
    }

    // ---- fused tree epilogue: trees -> weighted[row, 0..3] partials ----
    float wac[4][2] = {{0.f,0.f},{0.f,0.f},{0.f,0.f},{0.f,0.f}};
    #pragma unroll
    for (int j = 0; j < 2; ++j) {
        #pragma unroll
        for (int b = 0; b < 13; ++b) {
            const int cg = g * BN + warpN * 104 + b * 8 + q * 2;
            const float bias0 = bias_sm[cg], bias1 = bias_sm[cg + 1];
            const float fwv = fw_sm[cg >> 2];
            #pragma unroll
            for (int h = 0; h < 2; ++h) {
                const float s0 = acc[j][b][2 * h]     + bias0;
                const float s1 = acc[j][b][2 * h + 1] + bias1;
                const float sp = s0 + s1;
                const float S  = sp + __shfl_xor_sync(0xffffffffu, sp, 1);
                const float wS = fwv * S;
                wac[j * 2 + h][0] = fmaf(wS, sig_t(s0), wac[j * 2 + h][0]);
                wac[j * 2 + h][1] = fmaf(wS, sig_t(s1), wac[j * 2 + h][1]);
            }
        }
    }
    #pragma unroll
    for (int s = 0; s < 4; ++s) {        // combine tree halves (lanes q ^ 2)
        wac[s][0] += __shfl_xor_sync(0xffffffffu, wac[s][0], 2);
        wac[s][1] += __shfl_xor_sync(0xffffffffu, wac[s][1], 2);
    }

    // ---- cross-warpN reduction + partial FC + atomicAdd to out ----
    float* red = reinterpret_cast<float*>(smem + S_RED);
    __syncthreads();
    if (warpN == 1 && q < 2) {
        #pragma unroll
        for (int s = 0; s < 4; ++s) {
            const int rl = warpM * 32 + (s >> 1) * 16 + (s & 1) * 8 + rq;
            red[rl * 4 + q * 2]     = wac[s][0];
            red[rl * 4 + q * 2 + 1] = wac[s][1];
        }
    }
    __syncthreads();
    if (warpN == 0) {
        const float w00 = fw_sm[104], w01 = fw_sm[105], w02 = fw_sm[106], w03 = fw_sm[107];
        const float w10 = fw_sm[108], w11 = fw_sm[109], w12 = fw_sm[110], w13 = fw_sm[111];
        const float c0  = (g == 0) ? fw_sm[112] : 0.0f;
        const float c1  = (g == 0) ? fw_sm[113] : 0.0f;
        #pragma unroll
        for (int s = 0; s < 4; ++s) {
            const int rl = warpM * 32 + (s >> 1) * 16 + (s & 1) * 8 + rq;
            const int ki = (q & 1) * 2;
            const float v0 = wac[s][0] + red[rl * 4 + ki];
            const float v1 = wac[s][1] + red[rl * 4 + ki + 1];
            // partner lane (q^1) holds the other k-pair
            const float u0 = __shfl_xor_sync(0xffffffffu, v0, 1);
            const float u1 = __shfl_xor_sync(0xffffffffu, v1, 1);
            if (q == 0) {
                // k0=v0 k1=v1 k2=u0 k3=u1 -> this group's partial logits
                const float l0 = c0 + v0 * w00 + v1 * w01 + u0 * w02 + u1 * w03;
                const float l1 = c1 + v0 * w10 + v1 * w11 + u0 * w12 + u1 * w13;
                atomicAdd(out + 2 * (row0 + rl),     l0);
                atomicAdd(out + 2 * (row0 + rl) + 1, l1);
            }
        }
    }
}

// ---------------- launch ----------------------------------------------------
extern "C" void kernel_launch(void* const* d_in, const int* in_sizes, int n_in,
                              void* d_out, int out_size) {
    const float* x   = (const float*)d_in[0];
    const float* W1  = (const float*)d_in[1];
    const float* b1  = (const float*)d_in[2];
    const float* fw  = (const float*)d_in[3];
    const float* fcw = (const float*)d_in[4];
    const float* fcb = (const float*)d_in[5];
    float* out = (float*)d_out;

    cudaFuncSetAttribute(xgb_main, cudaFuncAttributeMaxDynamicSharedMemorySize, S_TOTAL);

    xgb_zero<<<64, 256>>>(out);                        // out: 65536 floats
    xgb_conv_w<<<104, 256>>>(W1);                      // convert + pad in one
    xgb_main<<<(BTOT / BM) * 2, NT, S_TOTAL>>>(x, b1, fw, fcw, fcb, out);
}

// round 17
// speedup vs baseline: 1.1171x; 1.0152x over previous
#include <cuda_runtime.h>
#include <cuda_fp16.h>
#include <cstdint>

// ============================================================================
// DifferentiableXGB — base-arch (compute_103), R16 + merged prep kernel.
// GEMM: split[B,416pad] = x[32768,1024] @ W1^T via mma.sync m16n8k16 f32.f16.
// Structure = R16 measured best (106.6us): 512 CTAs = 256 x-tiles x 2 tree-
// groups, NT=256 (warpM 0..3 x warpN 0..1, j=2, acc=104), BN=208 symmetric,
// reg-staged x, double-buffered A/B, fp16 inputs, fused tree epilogue +
// atomic FC (2 adds per out address onto 0 -> order-independent bit-exact).
// NEW: zero(out) + convert(W) + pad(W) merged into ONE prep kernel — the
// standalone xgb_zero launch measured 3.36us of pure launch latency.
// 2 kernel launches total.
// ============================================================================

static constexpr int BTOT  = 32768;
static constexpr int Dk    = 1024;
static constexpr int NPAD  = 416;    // 400 cols padded (pad trees have fw=0)
static constexpr int BN    = 208;    // cols per group-CTA (52 trees)
static constexpr int BM    = 128;
static constexpr int KC    = 64;     // k-chunk: 64 fp16 = 128B row (SW128)
static constexpr int NCHUNK= 16;
static constexpr int NT    = 256;

// smem byte offsets
static constexpr int S_BIAS = 0;        // 416 f
static constexpr int S_FW   = 1664;     // 104 fw + 8 fcw + 2 fcb
static constexpr int S_RED  = 4096;     // 128*4 f
static constexpr int S_A0   = 8192;     // 128*128B = 16384
static constexpr int S_A1   = 24576;
static constexpr int S_B0   = 40960;    // 208*128B = 26624
static constexpr int S_B1   = 67584;
static constexpr int S_TOTAL= 94208;

#define SW(o) ((o) ^ (((o) >> 3) & 0x70))

__device__ __align__(16) __half g_Wh[NPAD * Dk];   // 852 KB fp16 W scratch

// ---------------- asm helpers (all base-arch) ----------------
__device__ __forceinline__ uint32_t smem_u32(const void* p) {
    uint32_t a;
    asm("{ .reg .u64 t; cvta.to.shared.u64 t, %1; cvt.u32.u64 %0, t; }" : "=r"(a) : "l"(p));
    return a;
}
__device__ __forceinline__ void ldsm_x4(uint32_t (&r)[4], uint32_t addr) {
    asm volatile("ldmatrix.sync.aligned.m8n8.x4.shared.b16 {%0,%1,%2,%3}, [%4];"
                 : "=r"(r[0]), "=r"(r[1]), "=r"(r[2]), "=r"(r[3]) : "r"(addr));
}
__device__ __forceinline__ void ldsm_x2(uint32_t (&r)[2], uint32_t addr) {
    asm volatile("ldmatrix.sync.aligned.m8n8.x2.shared.b16 {%0,%1}, [%2];"
                 : "=r"(r[0]), "=r"(r[1]) : "r"(addr));
}
__device__ __forceinline__ void mma16816(float (&c)[4], const uint32_t (&a)[4],
                                         uint32_t b0, uint32_t b1) {
    asm volatile("mma.sync.aligned.m16n8k16.row.col.f32.f16.f16.f32 "
                 "{%0,%1,%2,%3}, {%4,%5,%6,%7}, {%8,%9}, {%0,%1,%2,%3};"
                 : "+f"(c[0]), "+f"(c[1]), "+f"(c[2]), "+f"(c[3])
                 : "r"(a[0]), "r"(a[1]), "r"(a[2]), "r"(a[3]), "r"(b0), "r"(b1));
}
__device__ __forceinline__ void cp16(uint32_t dst, const void* src) {
    asm volatile("cp.async.cg.shared.global [%0], [%1], 16;" :: "r"(dst), "l"(src));
}
__device__ __forceinline__ float sig_t(float v) {   // sigmoid via 1 MUFU (tanh)
    float t;
    asm("tanh.approx.f32 %0, %1;" : "=f"(t) : "f"(v * 0.5f));
    return fmaf(t, 0.5f, 0.5f);
}

// ---------------- kernel 1: prep = convert W + pad W + zero out -------------
__global__ void xgb_prep(const float* __restrict__ W1, float* __restrict__ out) {
    if (blockIdx.x < 100) {
        // convert: 100 blocks x 256 thr x 4 float4 = 400*1024 floats, MLP=4
        const int base = blockIdx.x * 1024 + threadIdx.x;
        float4 v[4];
        #pragma unroll
        for (int k = 0; k < 4; ++k)
            v[k] = reinterpret_cast<const float4*>(W1)[base + k * 256];
        #pragma unroll
        for (int k = 0; k < 4; ++k) {
            __half2 p0 = __float22half2_rn(make_float2(v[k].x, v[k].y));
            __half2 p1 = __float22half2_rn(make_float2(v[k].z, v[k].w));
            uint2 o;
            o.x = *reinterpret_cast<uint32_t*>(&p0);
            o.y = *reinterpret_cast<uint32_t*>(&p1);
            reinterpret_cast<uint2*>(g_Wh)[base + k * 256] = o;
        }
    } else if (blockIdx.x < 104) {
        // pad: 4 blocks zero W rows 400..415 (16*1024 halves = 4096 uint2)
        const int base = (blockIdx.x - 100) * 256 + threadIdx.x;   // 0..1023
        #pragma unroll
        for (int k = 0; k < 4; ++k)
            reinterpret_cast<uint2*>(g_Wh + 400 * Dk)[base + k * 1024] =
                make_uint2(0u, 0u);
    } else {
        // zero out: 64 blocks x 256 thr x float4 = 65536 floats (harness poisons)
        reinterpret_cast<float4*>(out)[(blockIdx.x - 104) * 256 + threadIdx.x] =
            make_float4(0.f, 0.f, 0.f, 0.f);
    }
}

// ---------------- kernel 2: GEMM + fused tree epilogue + atomic FC ----------
__global__ void __launch_bounds__(NT, 1)
xgb_main(const float* __restrict__ x, const float* __restrict__ b1,
         const float* __restrict__ fw, const float* __restrict__ fcw,
         const float* __restrict__ fcb, float* __restrict__ out) {
    extern __shared__ char smem[];
    const uint32_t smb = smem_u32(smem);
    const int tid  = threadIdx.x;
    const int lane = tid & 31;
    const int wid  = tid >> 5;
    const int warpM = wid & 3, warpN = wid >> 2;
    const int g     = blockIdx.x & 1;
    const int row0  = (blockIdx.x >> 1) * BM;
    const int q  = lane & 3;
    const int rq = lane >> 2;

    // constants to smem
    float* bias_sm = reinterpret_cast<float*>(smem + S_BIAS);
    float* fw_sm   = reinterpret_cast<float*>(smem + S_FW);
    for (int i = tid; i < NPAD; i += NT) bias_sm[i] = (i < 400) ? b1[i] : 0.0f;
    if (tid < 104) fw_sm[tid] = (tid < 100) ? fw[tid] : 0.0f;
    if (tid < 8)   fw_sm[104 + tid] = fcw[tid];
    if (tid < 2)   fw_sm[112 + tid] = fcb[tid];

    const __half* wsrc = g_Wh + (size_t)g * BN * Dk;

    // ---- prologue: chunk 0 ----
    float4 av[8];
    const int f4 = tid & 15, rb = tid >> 4;
    const float* xb0 = x + (size_t)(row0 + rb) * Dk + f4 * 4;
    #pragma unroll
    for (int r = 0; r < 8; ++r)
        av[r] = *reinterpret_cast<const float4*>(xb0 + (size_t)r * 16 * Dk);
    for (int i = tid; i < BN * 8; i += NT) {           // B(0) -> buf0
        const int row = i >> 3, c16 = i & 7;
        const uint32_t off = (uint32_t)(row * 128 + c16 * 16);
        cp16(smb + S_B0 + SW(off), wsrc + (size_t)row * Dk + c16 * 8);
    }
    asm volatile("cp.async.commit_group;" ::: "memory");
    #pragma unroll
    for (int r = 0; r < 8; ++r) {                      // A(0) -> buf0
        __half2 p0 = __float22half2_rn(make_float2(av[r].x, av[r].y));
        __half2 p1 = __float22half2_rn(make_float2(av[r].z, av[r].w));
        uint2 val;
        val.x = *reinterpret_cast<uint32_t*>(&p0);
        val.y = *reinterpret_cast<uint32_t*>(&p1);
        const uint32_t off = (uint32_t)((rb + 16 * r) * 128 + f4 * 8);
        *reinterpret_cast<uint2*>(smem + S_A0 + SW(off)) = val;
    }

    float acc[2][13][4];
    #pragma unroll
    for (int j = 0; j < 2; ++j)
        #pragma unroll
        for (int b = 0; b < 13; ++b)
            #pragma unroll
            for (int k = 0; k < 4; ++k) acc[j][b][k] = 0.0f;

    // ---- main K loop (one barrier per chunk) ----
    for (int c = 0; c < NCHUNK; ++c) {
        const uint32_t sA = (c & 1) ? S_A1 : S_A0;
        const uint32_t sB = (c & 1) ? S_B1 : S_B0;
        asm volatile("cp.async.wait_group 0;" ::: "memory");
        __syncthreads();                                // buf c ready; c-1 done

        if (c + 1 < NCHUNK) {                           // prefetch c+1
            const float* xbn = xb0 + (c + 1) * KC;
            #pragma unroll
            for (int r = 0; r < 8; ++r)
                av[r] = *reinterpret_cast<const float4*>(xbn + (size_t)r * 16 * Dk);
            const uint32_t sBn = (c & 1) ? S_B0 : S_B1;
            const __half* ws = wsrc + (c + 1) * KC;
            for (int i = tid; i < BN * 8; i += NT) {
                const int row = i >> 3, c16 = i & 7;
                const uint32_t off = (uint32_t)(row * 128 + c16 * 16);
                cp16(smb + sBn + SW(off), ws + (size_t)row * Dk + c16 * 8);
            }
            asm volatile("cp.async.commit_group;" ::: "memory");
        }

        // compute chunk c
        #pragma unroll
        for (int ks = 0; ks < 4; ++ks) {
            uint32_t a[2][4];
            #pragma unroll
            for (int j = 0; j < 2; ++j) {
                const uint32_t off = (uint32_t)((warpM * 32 + j * 16 + (lane & 15)) * 128
                                     + ks * 32 + ((lane >> 4) << 4));
                ldsm_x4(a[j], smb + sA + SW(off));
            }
            #pragma unroll
            for (int p = 0; p < 6; ++p) {
                uint32_t bq[4];
                const uint32_t rowb = (uint32_t)(warpN * 104 + p * 16 + (lane & 7)
                                     + ((lane >> 4) << 3));
                const uint32_t off = rowb * 128 + ks * 32 + (((lane >> 3) & 1) << 4);
                ldsm_x4(bq, smb + sB + SW(off));
                mma16816(acc[0][2 * p],     a[0], bq[0], bq[1]);
                mma16816(acc[0][2 * p + 1], a[0], bq[2], bq[3]);
                mma16816(acc[1][2 * p],     a[1], bq[0], bq[1]);
                mma16816(acc[1][2 * p + 1], a[1], bq[2], bq[3]);
            }
            {   // last n8 block (12)
                uint32_t b2[2];
                const uint32_t rowb = (uint32_t)(warpN * 104 + 96 + (lane & 7));
                const uint32_t off = rowb * 128 + ks * 32 + (((lane >> 3) & 1) << 4);
                ldsm_x2(b2, smb + sB + SW(off));
                mma16816(acc[0][12], a[0], b2[0], b2[1]);
                mma16816(acc[1][12], a[1], b2[0], b2[1]);
            }
        }

        if (c + 1 < NCHUNK) {
            // store A(c+1) into buffer last read at chunk c-1 — safe post-barrier
            const uint32_t sAn = (c & 1) ? S_A0 : S_A1;
            #pragma unroll
            for (int r = 0; r < 8; ++r) {
                __half2 p0 = __float22half2_rn(make_float2(av[r].x, av[r].y));
                __half2 p1 = __float22half2_rn(make_float2(av[r].z, av[r].w));
                uint2 val;
                val.x = *reinterpret_cast<uint32_t*>(&p0);
                val.y = *reinterpret_cast<uint32_t*>(&p1);
                const uint32_t off = (uint32_t)((rb + 16 * r) * 128 + f4 * 8);
                *reinterpret_cast<uint2*>(smem + sAn + SW(off)) = val;
            }
        }
    }

    // ---- fused tree epilogue: trees -> weighted[row, 0..3] partials ----
    float wac[4][2] = {{0.f,0.f},{0.f,0.f},{0.f,0.f},{0.f,0.f}};
    #pragma unroll
    for (int j = 0; j < 2; ++j) {
        #pragma unroll
        for (int b = 0; b < 13; ++b) {
            const int cg = g * BN + warpN * 104 + b * 8 + q * 2;
            const float bias0 = bias_sm[cg], bias1 = bias_sm[cg + 1];
            const float fwv = fw_sm[cg >> 2];
            #pragma unroll
            for (int h = 0; h < 2; ++h) {
                const float s0 = acc[j][b][2 * h]     + bias0;
                const float s1 = acc[j][b][2 * h + 1] + bias1;
                const float sp = s0 + s1;
                const float S  = sp + __shfl_xor_sync(0xffffffffu, sp, 1);
                const float wS = fwv * S;
                wac[j * 2 + h][0] = fmaf(wS, sig_t(s0), wac[j * 2 + h][0]);
                wac[j * 2 + h][1] = fmaf(wS, sig_t(s1), wac[j * 2 + h][1]);
            }
        }
    }
    #pragma unroll
    for (int s = 0; s < 4; ++s) {        // combine tree halves (lanes q ^ 2)
        wac[s][0] += __shfl_xor_sync(0xffffffffu, wac[s][0], 2);
        wac[s][1] += __shfl_xor_sync(0xffffffffu, wac[s][1], 2);
    }

    // ---- cross-warpN reduction + partial FC + atomicAdd to out ----
    float* red = reinterpret_cast<float*>(smem + S_RED);
    __syncthreads();
    if (warpN == 1 && q < 2) {
        #pragma unroll
        for (int s = 0; s < 4; ++s) {
            const int rl = warpM * 32 + (s >> 1) * 16 + (s & 1) * 8 + rq;
            red[rl * 4 + q * 2]     = wac[s][0];
            red[rl * 4 + q * 2 + 1] = wac[s][1];
        }
    }
    __syncthreads();
    if (warpN == 0) {
        const float w00 = fw_sm[104], w01 = fw_sm[105], w02 = fw_sm[106], w03 = fw_sm[107];
        const float w10 = fw_sm[108], w11 = fw_sm[109], w12 = fw_sm[110], w13 = fw_sm[111];
        const float c0  = (g == 0) ? fw_sm[112] : 0.0f;
        const float c1  = (g == 0) ? fw_sm[113] : 0.0f;
        #pragma unroll
        for (int s = 0; s < 4; ++s) {
            const int rl = warpM * 32 + (s >> 1) * 16 + (s & 1) * 8 + rq;
            const int ki = (q & 1) * 2;
            const float v0 = wac[s][0] + red[rl * 4 + ki];
            const float v1 = wac[s][1] + red[rl * 4 + ki + 1];
            // partner lane (q^1) holds the other k-pair
            const float u0 = __shfl_xor_sync(0xffffffffu, v0, 1);
            const float u1 = __shfl_xor_sync(0xffffffffu, v1, 1);
            if (q == 0) {
                // k0=v0 k1=v1 k2=u0 k3=u1 -> this group's partial logits
                const float l0 = c0 + v0 * w00 + v1 * w01 + u0 * w02 + u1 * w03;
                const float l1 = c1 + v0 * w10 + v1 * w11 + u0 * w12 + u1 * w13;
                atomicAdd(out + 2 * (row0 + rl),     l0);
                atomicAdd(out + 2 * (row0 + rl) + 1, l1);
            }
        }
    }
}

// ---------------- launch ----------------------------------------------------
extern "C" void kernel_launch(void* const* d_in, const int* in_sizes, int n_in,
                              void* d_out, int out_size) {
    const float* x   = (const float*)d_in[0];
    const float* W1  = (const float*)d_in[1];
    const float* b1  = (const float*)d_in[2];
    const float* fw  = (const float*)d_in[3];
    const float* fcw = (const float*)d_in[4];
    const float* fcb = (const float*)d_in[5];
    float* out = (float*)d_out;

    cudaFuncSetAttribute(xgb_main, cudaFuncAttributeMaxDynamicSharedMemorySize, S_TOTAL);

    xgb_prep<<<168, 256>>>(W1, out);                   // convert + pad + zero
    xgb_main<<<(BTOT / BM) * 2, NT, S_TOTAL>>>(x, b1, fw, fcw, fcb, out);
}